// round 5
// baseline (speedup 1.0000x reference)
#include <cuda_runtime.h>
#include <math.h>

// Problem constants
#define BATCH 4096
#define DIM   64

// Tiling: lane owns components i=lane and i=lane+32; R=2 rows per warp;
// 4 independent warps per CTA -> 8 rows/CTA, 512 CTAs, 2048 warps (13.8/SM).
#define R        2
#define WPB      4
#define THREADS  (WPB * 32)
#define ROWS_PER_BLOCK (R * WPB)                 // 8
#define NBLOCKS  (BATCH / ROWS_PER_BLOCK)        // 512

#define MAX_IT 100
#define DTOL   6e-4f

typedef unsigned long long u64;

__device__ __forceinline__ u64 pk(float lo, float hi) {
    u64 r; asm("mov.b64 %0, {%1, %2};" : "=l"(r) : "f"(lo), "f"(hi)); return r;
}
__device__ __forceinline__ void upk(float& lo, float& hi, u64 v) {
    asm("mov.b64 {%0, %1}, %2;" : "=f"(lo), "=f"(hi) : "l"(v));
}
// Packed dual-FMA on the FMA pipe: d.lo += a.lo*b.lo ; d.hi += a.hi*b.hi
__device__ __forceinline__ void fma2(u64& d, u64 a, u64 b) {
    asm("fma.rn.f32x2 %0, %1, %2, %0;" : "+l"(d) : "l"(a), "l"(b));
}

// Accurate tanh (~1e-6 abs err): MUFU.EX2 + MUFU.RCP, fast-math-proof.
__device__ __forceinline__ float my_tanh(float a) {
    float aa = fabsf(a);
    float e  = __expf(-2.0f * aa);                 // in (0, 1]
    float t  = __fdividef(1.0f - e, 1.0f + e);     // denom in [1,2]: safe
    return copysignf(t, a);
}

__global__ void __launch_bounds__(THREADS)
tanh_fixed_point_kernel(const float* __restrict__ x,
                        const float* __restrict__ W,
                        float* __restrict__ out)
{
    // Per-warp private z slices; warps never share -> __syncwarp only.
    __shared__ __align__(16) float zsh[WPB][R][DIM];

    const int tid  = threadIdx.x;
    const int lane = tid & 31;
    const int warp = tid >> 5;

    // W rows i=lane and i=lane+32 -> registers, packed consecutive-j pairs:
    //   wA[jc] = (W[lane][2jc],   W[lane][2jc+1])
    //   wB[jc] = (W[lane+32][2jc],W[lane+32][2jc+1])     (128 regs total)
    u64 wA[32], wB[32];
    {
        const ulonglong2* rowA = reinterpret_cast<const ulonglong2*>(W + lane * DIM);
        const ulonglong2* rowB = reinterpret_cast<const ulonglong2*>(W + (lane + 32) * DIM);
        #pragma unroll
        for (int q = 0; q < 16; q++) {
            ulonglong2 va = rowA[q];   // LDG.128, one-time, L2-hot
            ulonglong2 vb = rowB[q];
            wA[2 * q] = va.x; wA[2 * q + 1] = va.y;
            wB[2 * q] = vb.x; wB[2 * q + 1] = vb.y;
        }
    }

    const int row0 = blockIdx.x * ROWS_PER_BLOCK + warp * R;

    // Per-lane state: components i=lane ([0]) and i=lane+32 ([1]) per row
    float xr[R][2], z[R][2];
    #pragma unroll
    for (int r = 0; r < R; r++) {
        xr[r][0] = x[(row0 + r) * DIM + lane];
        xr[r][1] = x[(row0 + r) * DIM + lane + 32];
        z[r][0]  = my_tanh(xr[r][0]);
        z[r][1]  = my_tanh(xr[r][1]);
    }

    for (int it = 0; it < MAX_IT; it++) {
        #pragma unroll
        for (int r = 0; r < R; r++) {
            zsh[warp][r][lane]      = z[r][0];
            zsh[warp][r][lane + 32] = z[r][1];
        }
        __syncwarp();

        // 8 independent packed chains: (row, comp, even/odd-j)
        u64 acc0[R][2], acc1[R][2];
        #pragma unroll
        for (int r = 0; r < R; r++) {
            acc0[r][0] = pk(xr[r][0], 0.0f);  acc1[r][0] = pk(0.0f, 0.0f);
            acc0[r][1] = pk(xr[r][1], 0.0f);  acc1[r][1] = pk(0.0f, 0.0f);
        }

        // One z LDS.128 feeds 4 FMA2s (2 components x 2 j-pairs): ratio 1:4
        #pragma unroll
        for (int jq = 0; jq < 16; jq++) {
            #pragma unroll
            for (int r = 0; r < R; r++) {
                ulonglong2 zp = reinterpret_cast<const ulonglong2*>(zsh[warp][r])[jq];
                fma2(acc0[r][0], wA[2 * jq],     zp.x);
                fma2(acc1[r][0], wA[2 * jq + 1], zp.y);
                fma2(acc0[r][1], wB[2 * jq],     zp.x);
                fma2(acc1[r][1], wB[2 * jq + 1], zp.y);
            }
        }

        bool conv = true;
        #pragma unroll
        for (int r = 0; r < R; r++) {
            #pragma unroll
            for (int k = 0; k < 2; k++) {
                float a0, a1, b0, b1;
                upk(a0, a1, acc0[r][k]);
                upk(b0, b1, acc1[r][k]);
                float n = my_tanh((a0 + b0) + (a1 + b1));
                conv = conv && (fabsf(n - z[r][k]) < DTOL);
                z[r][k] = n;
            }
        }

        __syncwarp();   // reads done before next iteration's stores
        if (__all_sync(0xffffffffu, conv)) break;
    }

    #pragma unroll
    for (int r = 0; r < R; r++) {
        out[(row0 + r) * DIM + lane]      = z[r][0];
        out[(row0 + r) * DIM + lane + 32] = z[r][1];
    }
}

extern "C" void kernel_launch(void* const* d_in, const int* in_sizes, int n_in,
                              void* d_out, int out_size)
{
    const float* x = (const float*)d_in[0];   // [4096, 64]
    const float* W = (const float*)d_in[1];   // [64, 64]
    float* out = (float*)d_out;               // [4096, 64]
    (void)in_sizes; (void)n_in; (void)out_size;

    tanh_fixed_point_kernel<<<NBLOCKS, THREADS>>>(x, W, out);
}

// round 6
// speedup vs baseline: 1.3047x; 1.3047x over previous
#include <cuda_runtime.h>
#include <math.h>

// Problem constants
#define BATCH 4096
#define DIM   64

// Tiling: lane owns components i=lane, i=lane+32; R=2 rows per warp;
// 4 independent warps per CTA -> 8 rows/CTA, 512 CTAs, 2048 warps (~13.8/SM).
#define R        2
#define WPB      4
#define THREADS  (WPB * 32)
#define ROWS_PER_BLOCK (R * WPB)                 // 8
#define NBLOCKS  (BATCH / ROWS_PER_BLOCK)        // 512

#define MAX_IT 100
#define DTOL   6e-4f

#define WPITCH 68   // staging pitch: word addr 68*l -> 4l mod 32 per phase: conflict-free LDS.128

typedef unsigned long long u64;

__device__ __forceinline__ u64 pk(float lo, float hi) {
    u64 r; asm("mov.b64 %0, {%1, %2};" : "=l"(r) : "f"(lo), "f"(hi)); return r;
}
__device__ __forceinline__ void upk(float& lo, float& hi, u64 v) {
    asm("mov.b64 {%0, %1}, %2;" : "=f"(lo), "=f"(hi) : "l"(v));
}
// Packed dual-FMA on the FMA pipe: d.lo += a.lo*b.lo ; d.hi += a.hi*b.hi
__device__ __forceinline__ void fma2(u64& d, u64 a, u64 b) {
    asm("fma.rn.f32x2 %0, %1, %2, %0;" : "+l"(d) : "l"(a), "l"(b));
}

// Accurate tanh (~1e-6 abs err): MUFU.EX2 + MUFU.RCP, fast-math-proof.
__device__ __forceinline__ float my_tanh(float a) {
    float aa = fabsf(a);
    float e  = __expf(-2.0f * aa);                 // in (0, 1]
    float t  = __fdividef(1.0f - e, 1.0f + e);     // denom in [1,2]: safe
    return copysignf(t, a);
}

__global__ void __launch_bounds__(THREADS)
tanh_fixed_point_kernel(const float* __restrict__ x,
                        const float* __restrict__ W,
                        float* __restrict__ out)
{
    // W staging (one-time) + ping-pong per-warp z slices.
    __shared__ __align__(16) float Wsh[DIM * WPITCH];
    __shared__ __align__(16) float zsh[2][WPB][R][DIM];

    const int tid  = threadIdx.x;
    const int lane = tid & 31;
    const int warp = tid >> 5;

    // Coalesced one-time stage of W into shared (LDG: 128 consecutive floats/step)
    for (int idx = tid; idx < DIM * DIM; idx += THREADS) {
        int i = idx >> 6;
        int j = idx & 63;
        Wsh[i * WPITCH + j] = W[idx];
    }
    __syncthreads();

    // W rows i=lane and i=lane+32 -> registers as packed consecutive-j pairs
    // (conflict-free strided LDS.128 from the pitch-68 staging buffer).
    u64 wA[32], wB[32];
    {
        const ulonglong2* rowA = reinterpret_cast<const ulonglong2*>(&Wsh[lane * WPITCH]);
        const ulonglong2* rowB = reinterpret_cast<const ulonglong2*>(&Wsh[(lane + 32) * WPITCH]);
        #pragma unroll
        for (int q = 0; q < 16; q++) {
            ulonglong2 va = rowA[q];
            ulonglong2 vb = rowB[q];
            wA[2 * q] = va.x; wA[2 * q + 1] = va.y;
            wB[2 * q] = vb.x; wB[2 * q + 1] = vb.y;
        }
    }

    const int row0 = blockIdx.x * ROWS_PER_BLOCK + warp * R;

    // Per-lane state: components i=lane ([0]) and i=lane+32 ([1]) per row
    float xr[R][2], z[R][2];
    #pragma unroll
    for (int r = 0; r < R; r++) {
        xr[r][0] = x[(row0 + r) * DIM + lane];          // coalesced
        xr[r][1] = x[(row0 + r) * DIM + lane + 32];
        z[r][0]  = my_tanh(xr[r][0]);
        z[r][1]  = my_tanh(xr[r][1]);
        zsh[0][warp][r][lane]      = z[r][0];
        zsh[0][warp][r][lane + 32] = z[r][1];
    }
    __syncwarp();

    int p = 0;
    for (int it = 0; it < MAX_IT; it++) {
        // 8 independent packed chains, depth 16: (row, comp, even/odd j-pair)
        u64 acc0[R][2], acc1[R][2];
        #pragma unroll
        for (int r = 0; r < R; r++) {
            acc0[r][0] = pk(xr[r][0], 0.0f);  acc1[r][0] = pk(0.0f, 0.0f);
            acc0[r][1] = pk(xr[r][1], 0.0f);  acc1[r][1] = pk(0.0f, 0.0f);
        }

        // One z LDS.128 (broadcast) feeds 4 FMA2s: reuse ratio 1:4
        #pragma unroll
        for (int jq = 0; jq < 16; jq++) {
            #pragma unroll
            for (int r = 0; r < R; r++) {
                ulonglong2 zp = reinterpret_cast<const ulonglong2*>(zsh[p][warp][r])[jq];
                fma2(acc0[r][0], wA[2 * jq],     zp.x);
                fma2(acc1[r][0], wA[2 * jq + 1], zp.y);
                fma2(acc0[r][1], wB[2 * jq],     zp.x);
                fma2(acc1[r][1], wB[2 * jq + 1], zp.y);
            }
        }

        bool conv = true;
        #pragma unroll
        for (int r = 0; r < R; r++) {
            #pragma unroll
            for (int k = 0; k < 2; k++) {
                float a0, a1, b0, b1;
                upk(a0, a1, acc0[r][k]);
                upk(b0, b1, acc1[r][k]);
                float n = my_tanh((a0 + b0) + (a1 + b1));
                conv = conv && (fabsf(n - z[r][k]) < DTOL);
                z[r][k] = n;
            }
            // store new z into the other buffer (ping-pong -> single sync/iter)
            zsh[p ^ 1][warp][r][lane]      = z[r][0];
            zsh[p ^ 1][warp][r][lane + 32] = z[r][1];
        }

        p ^= 1;
        __syncwarp();   // orders this iter's stores before next iter's loads
        if (__all_sync(0xffffffffu, conv)) break;
    }

    #pragma unroll
    for (int r = 0; r < R; r++) {
        out[(row0 + r) * DIM + lane]      = z[r][0];
        out[(row0 + r) * DIM + lane + 32] = z[r][1];
    }
}

extern "C" void kernel_launch(void* const* d_in, const int* in_sizes, int n_in,
                              void* d_out, int out_size)
{
    const float* x = (const float*)d_in[0];   // [4096, 64]
    const float* W = (const float*)d_in[1];   // [64, 64]
    float* out = (float*)d_out;               // [4096, 64]
    (void)in_sizes; (void)n_in; (void)out_size;

    tanh_fixed_point_kernel<<<NBLOCKS, THREADS>>>(x, W, out);
}

// round 7
// speedup vs baseline: 1.5310x; 1.1735x over previous
#include <cuda_runtime.h>
#include <math.h>

// Problem constants
#define BATCH 4096
#define DIM   64

// Tiling: lane owns components i=lane, i=lane+32; R=4 rows per warp;
// WPB=2 warps per CTA -> 8 rows/CTA, 512 CTAs (wave-balanced: 4/3 per SM),
// 1024 warps total, 16 independent FMA chains per warp.
#define R        4
#define WPB      2
#define THREADS  (WPB * 32)
#define ROWS_PER_BLOCK (R * WPB)                 // 8
#define NBLOCKS  (BATCH / ROWS_PER_BLOCK)        // 512

#define MAX_IT 100
#define DTOL   2e-3f

#define WPITCH 68   // staging pitch: conflict-free strided LDS.128

typedef unsigned long long u64;

__device__ __forceinline__ u64 pk(float lo, float hi) {
    u64 r; asm("mov.b64 %0, {%1, %2};" : "=l"(r) : "f"(lo), "f"(hi)); return r;
}
__device__ __forceinline__ void upk(float& lo, float& hi, u64 v) {
    asm("mov.b64 {%0, %1}, %2;" : "=f"(lo), "=f"(hi) : "l"(v));
}
// Packed dual-FMA on the FMA pipe: d.lo += a.lo*b.lo ; d.hi += a.hi*b.hi
__device__ __forceinline__ void fma2(u64& d, u64 a, u64 b) {
    asm("fma.rn.f32x2 %0, %1, %2, %0;" : "+l"(d) : "l"(a), "l"(b));
}

// tanh with ONE MUFU (EX2) + Newton-refined reciprocal (div-free).
// e = e^{-2|a|} in (0,1]; d = 1+e in [1,2]; linear seed for 1/d (max rel
// err ~3e-2) then 2 Newton steps -> rel err ~8e-7. Total abs err ~1e-6.
__device__ __forceinline__ float my_tanh(float a) {
    float aa = fabsf(a);
    float e;
    asm("ex2.approx.ftz.f32 %0, %1;" : "=f"(e) : "f"(aa * -2.8853900817779268f));
    float d = 1.0f + e;
    float r = fmaf(-0.49043f, d, 1.4571f);   // seed for 1/d on [1,2]
    r = r * (2.0f - d * r);                   // Newton 1
    r = r * (2.0f - d * r);                   // Newton 2
    float t = (1.0f - e) * r;
    return copysignf(t, a);
}

__global__ void __launch_bounds__(THREADS)
tanh_fixed_point_kernel(const float* __restrict__ x,
                        const float* __restrict__ W,
                        float* __restrict__ out)
{
    __shared__ __align__(16) float Wsh[DIM * WPITCH];      // one-time stage
    __shared__ __align__(16) float zsh[2][WPB][R][DIM];    // ping-pong z

    const int tid  = threadIdx.x;
    const int lane = tid & 31;
    const int warp = tid >> 5;

    // Coalesced one-time stage of W into shared
    for (int idx = tid; idx < DIM * DIM; idx += THREADS) {
        int i = idx >> 6;
        int j = idx & 63;
        Wsh[i * WPITCH + j] = W[idx];
    }
    __syncthreads();

    // W rows i=lane, i=lane+32 -> registers as packed consecutive-j pairs
    u64 wA[32], wB[32];
    {
        const ulonglong2* rowA = reinterpret_cast<const ulonglong2*>(&Wsh[lane * WPITCH]);
        const ulonglong2* rowB = reinterpret_cast<const ulonglong2*>(&Wsh[(lane + 32) * WPITCH]);
        #pragma unroll
        for (int q = 0; q < 16; q++) {
            ulonglong2 va = rowA[q];
            ulonglong2 vb = rowB[q];
            wA[2 * q] = va.x; wA[2 * q + 1] = va.y;
            wB[2 * q] = vb.x; wB[2 * q + 1] = vb.y;
        }
    }

    const int row0 = blockIdx.x * ROWS_PER_BLOCK + warp * R;

    float xr[R][2], z[R][2];
    #pragma unroll
    for (int r = 0; r < R; r++) {
        xr[r][0] = x[(row0 + r) * DIM + lane];          // coalesced
        xr[r][1] = x[(row0 + r) * DIM + lane + 32];
        z[r][0]  = my_tanh(xr[r][0]);
        z[r][1]  = my_tanh(xr[r][1]);
        zsh[0][warp][r][lane]      = z[r][0];
        zsh[0][warp][r][lane + 32] = z[r][1];
    }
    __syncwarp();

    int p = 0;
    for (int it = 0; it < MAX_IT; it++) {
        // 16 independent packed chains, depth 16: (row, comp, even/odd j-pair)
        u64 acc0[R][2], acc1[R][2];
        #pragma unroll
        for (int r = 0; r < R; r++) {
            acc0[r][0] = pk(xr[r][0], 0.0f);  acc1[r][0] = pk(0.0f, 0.0f);
            acc0[r][1] = pk(xr[r][1], 0.0f);  acc1[r][1] = pk(0.0f, 0.0f);
        }

        // One z LDS.128 (broadcast) feeds 4 FMA2s: reuse 1:4
        #pragma unroll
        for (int jq = 0; jq < 16; jq++) {
            #pragma unroll
            for (int r = 0; r < R; r++) {
                ulonglong2 zp = reinterpret_cast<const ulonglong2*>(zsh[p][warp][r])[jq];
                fma2(acc0[r][0], wA[2 * jq],     zp.x);
                fma2(acc1[r][0], wA[2 * jq + 1], zp.y);
                fma2(acc0[r][1], wB[2 * jq],     zp.x);
                fma2(acc1[r][1], wB[2 * jq + 1], zp.y);
            }
        }

        bool conv = true;
        #pragma unroll
        for (int r = 0; r < R; r++) {
            #pragma unroll
            for (int k = 0; k < 2; k++) {
                float a0, a1, b0, b1;
                upk(a0, a1, acc0[r][k]);
                upk(b0, b1, acc1[r][k]);
                float n = my_tanh((a0 + b0) + (a1 + b1));
                conv = conv && (fabsf(n - z[r][k]) < DTOL);
                z[r][k] = n;
            }
            zsh[p ^ 1][warp][r][lane]      = z[r][0];
            zsh[p ^ 1][warp][r][lane + 32] = z[r][1];
        }

        p ^= 1;
        __syncwarp();   // orders stores(k) before loads(k+1); single sync/iter
        if (__all_sync(0xffffffffu, conv)) break;
    }

    #pragma unroll
    for (int r = 0; r < R; r++) {
        out[(row0 + r) * DIM + lane]      = z[r][0];
        out[(row0 + r) * DIM + lane + 32] = z[r][1];
    }
}

extern "C" void kernel_launch(void* const* d_in, const int* in_sizes, int n_in,
                              void* d_out, int out_size)
{
    const float* x = (const float*)d_in[0];   // [4096, 64]
    const float* W = (const float*)d_in[1];   // [64, 64]
    float* out = (float*)d_out;               // [4096, 64]
    (void)in_sizes; (void)n_in; (void)out_size;

    tanh_fixed_point_kernel<<<NBLOCKS, THREADS>>>(x, W, out);
}